// round 16
// baseline (speedup 1.0000x reference)
#include <cuda_runtime.h>
#include <cuda_fp16.h>
#include <cstdint>

#define T_SEQ  2048
#define NB     4
#define NH     12
#define DH     64
#define DMODEL 768
#define BHN    (NB * NH)   // 48

// 8 * log2(e): softmax computed in base-2 domain
#define QSCALE 11.5415603f

// ---------------------------------------------------------------------------
// Device-global scratch. fp16 hi/lo splits (lo only where needed).
// ---------------------------------------------------------------------------
__device__ uint16_t g_xh[(size_t)NB * T_SEQ * DMODEL];
__device__ uint16_t g_xl[(size_t)NB * T_SEQ * DMODEL];
__device__ uint16_t g_wqh[(size_t)3 * DMODEL * DMODEL];
__device__ uint16_t g_wql[(size_t)3 * DMODEL * DMODEL];
__device__ uint16_t g_woh[(size_t)DMODEL * DMODEL];

__device__ uint16_t g_qh[(size_t)BHN * T_SEQ * DH];   // Q pre-scaled by 8*log2(e)
__device__ uint16_t g_ql[(size_t)BHN * T_SEQ * DH];
__device__ uint16_t g_kh[(size_t)BHN * T_SEQ * DH];
__device__ uint16_t g_kl[(size_t)BHN * T_SEQ * DH];
__device__ uint16_t g_vth[(size_t)BHN * DH * T_SEQ];  // V^T: [bh][dh][t] (hi only)

__device__ uint16_t g_oh[(size_t)NB * T_SEQ * DMODEL]; // attention out (hi only)

// ---------------------------------------------------------------------------
// Helpers
// ---------------------------------------------------------------------------
__device__ __forceinline__ uint32_t smem_u32(const void* p) {
    uint32_t a;
    asm("{ .reg .u64 t; cvta.to.shared.u64 t, %1; cvt.u32.u64 %0, t; }"
        : "=r"(a) : "l"(p));
    return a;
}

__device__ __forceinline__ float ex2f(float x) {
    float y;
    asm("ex2.approx.f32 %0, %1;" : "=f"(y) : "f"(x));
    return y;
}

__device__ __forceinline__ uint32_t packh2(float x0, float x1) {
    __half2 hh = __floats2half2_rn(x0, x1);
    return *reinterpret_cast<uint32_t*>(&hh);
}

__device__ __forceinline__ void split2(float x0, float x1, uint32_t& h, uint32_t& l) {
    __half2 hh = __floats2half2_rn(x0, x1);
    __half2 ll = __floats2half2_rn(x0 - __low2float(hh), x1 - __high2float(hh));
    h = *reinterpret_cast<uint32_t*>(&hh);
    l = *reinterpret_cast<uint32_t*>(&ll);
}

// m16n8k16 fp16 mma, fp32 accum (non-volatile: schedulable).
__device__ __forceinline__ void mma_f16(float* d, const uint32_t* a, uint32_t b0, uint32_t b1) {
    asm("mma.sync.aligned.m16n8k16.row.col.f32.f16.f16.f32 "
        "{%0,%1,%2,%3}, {%4,%5,%6,%7}, {%8,%9}, {%0,%1,%2,%3};"
        : "+f"(d[0]), "+f"(d[1]), "+f"(d[2]), "+f"(d[3])
        : "r"(a[0]), "r"(a[1]), "r"(a[2]), "r"(a[3]), "r"(b0), "r"(b1));
}

// ldmatrix x4 (volatile: preserves ordering vs smem writes/barriers)
__device__ __forceinline__ void ldsm4(uint32_t* r, uint32_t addr) {
    asm volatile("ldmatrix.sync.aligned.m8n8.x4.shared.b16 {%0,%1,%2,%3}, [%4];"
                 : "=r"(r[0]), "=r"(r[1]), "=r"(r[2]), "=r"(r[3]) : "r"(addr));
}

// Swizzled smem byte offset within a tile of 128B rows
__device__ __forceinline__ uint32_t swz(int row, int byteoff) {
    return (uint32_t)(row * 128 + (byteoff ^ ((row & 7) << 4)));
}

#define CP_ASYNC16(dst_u32, src_ptr) \
    asm volatile("cp.async.cg.shared.global [%0], [%1], 16;" \
                 :: "r"(dst_u32), "l"(src_ptr) : "memory")
#define CP_COMMIT() asm volatile("cp.async.commit_group;" ::: "memory")
#define CP_WAIT1()  asm volatile("cp.async.wait_group 1;" ::: "memory")
#define CP_WAIT0()  asm volatile("cp.async.wait_group 0;" ::: "memory")

// ---------------------------------------------------------------------------
// Split fp32 -> fp16 (hi, lo); w_out keeps hi only.
// ---------------------------------------------------------------------------
__global__ void split_all(const float* __restrict__ x, const float* __restrict__ wq,
                          const float* __restrict__ wo) {
    const int N1 = (NB * T_SEQ * DMODEL) / 4;
    const int N2 = (3 * DMODEL * DMODEL) / 4;
    const int N3 = (DMODEL * DMODEL) / 4;
    const int tot = N1 + N2 + N3;
    for (int i = blockIdx.x * blockDim.x + threadIdx.x; i < tot; i += gridDim.x * blockDim.x) {
        const float4* src;
        uint16_t *dh, *dl;
        int j;
        if (i < N1)           { src = (const float4*)x;  j = i;           dh = g_xh;  dl = g_xl; }
        else if (i < N1 + N2) { src = (const float4*)wq; j = i - N1;      dh = g_wqh; dl = g_wql; }
        else                  { src = (const float4*)wo; j = i - N1 - N2; dh = g_woh; dl = nullptr; }
        float4 v = src[j];
        uint32_t h0, l0, h1, l1;
        split2(v.x, v.y, h0, l0);
        split2(v.z, v.w, h1, l1);
        *reinterpret_cast<uint2*>(dh + 4 * (size_t)j) = uint2{h0, h1};
        if (dl) *reinterpret_cast<uint2*>(dl + 4 * (size_t)j) = uint2{l0, l1};
    }
}

// ---------------------------------------------------------------------------
// mma.sync split-fp16 GEMM, cp.async double-buffered, ldmatrix fragments,
// register-level software pipelining; single barrier per K-chunk.
// CTA 128x64, 128 thr, warps 2m x 2n, warp tile 64x32.
// MODE 0: Q,K columns of QKV (grid.y = 24). 3-term.  Stage 96KB.
// MODE 2: V columns of QKV (grid.y = 12). 1-term.    Stage 48KB.
// MODE 1: output projection (grid.y = 12). 1-term.   Stage 48KB.
// ---------------------------------------------------------------------------
template <int MODE>
__global__ void __launch_bounds__(128) gemm_mma(float* __restrict__ C) {
    extern __shared__ char smem[];
    const uint32_t sb = smem_u32(smem);
    constexpr int CTAM = 128, CTAN = 64, NTHR = 128;
    constexpr int MT = 4;
    constexpr bool T3 = (MODE == 0);
    constexpr int NB_A = T3 ? 2 : 1;
    constexpr int NB_B = T3 ? 2 : 1;
    constexpr int AREG = NB_A * CTAM * 128;
    constexpr int AHo = 0, ALo = CTAM * 128;
    constexpr int BHo = AREG, BLo = AREG + CTAN * 128;
    constexpr int STAGE = AREG + NB_B * CTAN * 128;

    const int tid = threadIdx.x;
    const int lane = tid & 31;
    const int wid = tid >> 5;
    const int m0 = blockIdx.x * CTAM;
    const int by = blockIdx.y;
    const int koff = (MODE == 2) ? (24 + by) : by;   // QKV column group
    const int wm = (wid >> 1) * 64;
    const int wn = (wid & 1) * 32;

    const int laA = lane & 15;
    const int lbA = (lane >> 4) * 16;
    const int laB = (lane >> 4) * 8 + (lane & 7);
    const int lbB = ((lane >> 3) & 1) * 16;

    const uint16_t* Ah = (MODE == 1) ? g_oh : g_xh;
    const uint16_t* Al = g_xl;
    const uint16_t* Bh = (MODE == 1) ? g_woh : g_wqh;
    const uint16_t* Bl = g_wql;

    auto issue_stage = [&](int c, int buf) {
        const int k0 = c * 64;
        const uint32_t base = sb + buf * STAGE;
#pragma unroll
        for (int it = 0; it < CTAM * 8 / NTHR; it++) {
            const int idx = it * NTHR + tid;
            const int row = idx >> 3;
            const int ch = idx & 7;
            const uint32_t so = swz(row, ch * 16);
            CP_ASYNC16(base + AHo + so, Ah + (size_t)(m0 + row) * DMODEL + k0 + ch * 8);
            if (T3)
                CP_ASYNC16(base + ALo + so, Al + (size_t)(m0 + row) * DMODEL + k0 + ch * 8);
        }
#pragma unroll
        for (int it = 0; it < CTAN * 8 / NTHR; it++) {
            const int idx = it * NTHR + tid;
            const int row = idx >> 3;
            const int ch = idx & 7;
            const uint32_t so = swz(row, ch * 16);
            const int grow = (MODE == 1) ? (by * CTAN + row) : (row * 36 + koff);
            CP_ASYNC16(base + BHo + so, Bh + (size_t)grow * DMODEL + k0 + ch * 8);
            if (T3)
                CP_ASYNC16(base + BLo + so, Bl + (size_t)grow * DMODEL + k0 + ch * 8);
        }
        CP_COMMIT();
    };

    float acc[MT][4][4];
#pragma unroll
    for (int mt = 0; mt < MT; mt++)
#pragma unroll
        for (int nt = 0; nt < 4; nt++)
#pragma unroll
            for (int q = 0; q < 4; q++) acc[mt][nt][q] = 0.0f;

    issue_stage(0, 0);

    for (int c = 0; c < 12; c++) {
        CP_WAIT0();                 // only stage c outstanding at this point
        __syncthreads();            // CTA-wide visibility + buffer reuse safety
        if (c + 1 < 12) issue_stage(c + 1, (c + 1) & 1);
        const uint32_t bpu = sb + (c & 1) * STAGE;

        uint32_t aH[2][MT][4], aL[2][MT][4], bH[2][2][4], bL[2][2][4];
        auto ldkt = [&](int kt, int p) {
#pragma unroll
            for (int mt = 0; mt < MT; mt++) {
                const uint32_t soA = swz(wm + mt * 16 + laA, kt * 32 + lbA);
                ldsm4(aH[p][mt], bpu + AHo + soA);
                if (T3) ldsm4(aL[p][mt], bpu + ALo + soA);
            }
#pragma unroll
            for (int ntp = 0; ntp < 2; ntp++) {
                const uint32_t soB = swz(wn + ntp * 16 + laB, kt * 32 + lbB);
                ldsm4(bH[p][ntp], bpu + BHo + soB);
                if (T3) ldsm4(bL[p][ntp], bpu + BLo + soB);
            }
        };
        ldkt(0, 0);

#pragma unroll
        for (int kt = 0; kt < 4; kt++) {
            const int p = kt & 1;
            if (kt < 3) ldkt(kt + 1, p ^ 1);
#pragma unroll
            for (int ntp = 0; ntp < 2; ntp++) {
#pragma unroll
                for (int mt = 0; mt < MT; mt++) {
                    mma_f16(acc[mt][2 * ntp],     aH[p][mt], bH[p][ntp][0], bH[p][ntp][1]);
                    mma_f16(acc[mt][2 * ntp + 1], aH[p][mt], bH[p][ntp][2], bH[p][ntp][3]);
                }
                if (T3) {
#pragma unroll
                    for (int mt = 0; mt < MT; mt++) {
                        mma_f16(acc[mt][2 * ntp],     aH[p][mt], bL[p][ntp][0], bL[p][ntp][1]);
                        mma_f16(acc[mt][2 * ntp + 1], aH[p][mt], bL[p][ntp][2], bL[p][ntp][3]);
                    }
#pragma unroll
                    for (int mt = 0; mt < MT; mt++) {
                        mma_f16(acc[mt][2 * ntp],     aL[p][mt], bH[p][ntp][0], bH[p][ntp][1]);
                        mma_f16(acc[mt][2 * ntp + 1], aL[p][mt], bH[p][ntp][2], bH[p][ntp][3]);
                    }
                }
            }
        }
    }

    // Epilogue
    const int r = lane >> 2;
#pragma unroll
    for (int mt = 0; mt < MT; mt++) {
        const int mrow = m0 + wm + mt * 16 + r;
#pragma unroll
        for (int nt = 0; nt < 4; nt++) {
            const int nl = wn + nt * 8 + 2 * (lane & 3);
            float d0 = acc[mt][nt][0], d1 = acc[mt][nt][1];
            float d2 = acc[mt][nt][2], d3 = acc[mt][nt][3];
            if (MODE != 1) {
                const int dh = nl;
                const int k3 = koff / 12;
                const int h = koff - 12 * k3;
                const int b = mrow >> 11;
                const int t = mrow & 2047;
                const int bhI = b * NH + h;
                if (k3 == 0) { d0 *= QSCALE; d1 *= QSCALE; d2 *= QSCALE; d3 *= QSCALE; }
                if (MODE == 2) {
                    uint32_t h0 = packh2(d0, d1), h1 = packh2(d2, d3);
                    size_t q0 = ((size_t)bhI * DH + dh) * T_SEQ + t;
                    size_t q1 = ((size_t)bhI * DH + dh + 1) * T_SEQ + t;
                    g_vth[q0] = (uint16_t)h0;      g_vth[q1] = (uint16_t)(h0 >> 16);
                    g_vth[q0 + 8] = (uint16_t)h1;  g_vth[q1 + 8] = (uint16_t)(h1 >> 16);
                } else {
                    uint32_t h0, l0, h1, l1;
                    split2(d0, d1, h0, l0);
                    split2(d2, d3, h1, l1);
                    uint16_t* dsth = (k3 == 0) ? g_qh : g_kh;
                    uint16_t* dstl = (k3 == 0) ? g_ql : g_kl;
                    size_t p0 = ((size_t)bhI * T_SEQ + t) * DH + dh;
                    size_t p1 = ((size_t)bhI * T_SEQ + t + 8) * DH + dh;
                    *reinterpret_cast<uint32_t*>(dsth + p0) = h0;
                    *reinterpret_cast<uint32_t*>(dstl + p0) = l0;
                    *reinterpret_cast<uint32_t*>(dsth + p1) = h1;
                    *reinterpret_cast<uint32_t*>(dstl + p1) = l1;
                }
            } else {
                float2 p0{d0, d1}, p1{d2, d3};
                *reinterpret_cast<float2*>(C + (size_t)mrow * DMODEL + by * CTAN + nl) = p0;
                *reinterpret_cast<float2*>(C + (size_t)(mrow + 8) * DMODEL + by * CTAN + nl) = p1;
            }
        }
    }
}

// ---------------------------------------------------------------------------
// Flash attention (round-15 state, measured fastest).
// 128 threads (4 warps), warp tile 32 q-rows x 64 keys.
// QK^T 3-term, PV single-term. Base-2 softmax. 3-stage cp.async KV ring.
// ---------------------------------------------------------------------------
#define ATTN_KV_BUF   24576
#define ATTN_SMEM_BYTES (32768 + 3 * ATTN_KV_BUF)   // Q(32K) + 3 KV stages

__global__ void __launch_bounds__(128) attn_mma() {
    extern __shared__ char smem[];
    const uint32_t sb = smem_u32(smem);
    const int QHo = 0, QLo = 16384;
    const int KHo = 0, KLo = 8192, VHo = 16384;     // within KV stage

    const int tid = threadIdx.x;
    const int lane = tid & 31;
    const int wid = tid >> 5;
    const int r = lane >> 2;
    const int bh = blockIdx.y;
    const int t0 = blockIdx.x * 128;
    const int wrow = wid * 32;

    const int laA = lane & 15;
    const int lbA = (lane >> 4) * 16;
    const int laB = (lane >> 4) * 8 + (lane & 7);
    const int lbB = ((lane >> 3) & 1) * 16;

    const uint16_t* kh = g_kh + (size_t)bh * T_SEQ * DH;
    const uint16_t* kl = g_kl + (size_t)bh * T_SEQ * DH;
    const uint16_t* vh = g_vth + (size_t)bh * DH * T_SEQ;

    auto issue_kv = [&](int kt, int buf) {
        const uint32_t base = sb + 32768 + buf * ATTN_KV_BUF;
#pragma unroll
        for (int it = 0; it < 4; it++) {
            const int idx = it * 128 + tid;
            const int row = idx >> 3;
            const int ch = idx & 7;
            const uint32_t so = swz(row, ch * 16);
            CP_ASYNC16(base + KHo + so, kh + (size_t)(kt * 64 + row) * DH + ch * 8);
            CP_ASYNC16(base + KLo + so, kl + (size_t)(kt * 64 + row) * DH + ch * 8);
            CP_ASYNC16(base + VHo + so, vh + (size_t)row * T_SEQ + kt * 64 + ch * 8);
        }
        CP_COMMIT();
    };

    issue_kv(0, 0);
    issue_kv(1, 1);

    const uint16_t* qhp = g_qh + ((size_t)bh * T_SEQ + t0) * DH;
    const uint16_t* qlp = g_ql + ((size_t)bh * T_SEQ + t0) * DH;
#pragma unroll
    for (int it = 0; it < 8; it++) {
        const int idx = it * 128 + tid;
        const int row = idx >> 3;
        const int ch = idx & 7;
        const uint32_t so = swz(row, ch * 16);
        *reinterpret_cast<uint4*>(smem + QHo + so) =
            *(reinterpret_cast<const uint4*>(qhp + (size_t)row * DH) + ch);
        *reinterpret_cast<uint4*>(smem + QLo + so) =
            *(reinterpret_cast<const uint4*>(qlp + (size_t)row * DH) + ch);
    }

    float mS[2][2], lS[2][2];
#pragma unroll
    for (int mt = 0; mt < 2; mt++) { mS[mt][0] = mS[mt][1] = -1e30f; lS[mt][0] = lS[mt][1] = 0.0f; }

    float o[2][8][4];
#pragma unroll
    for (int mt = 0; mt < 2; mt++)
#pragma unroll
        for (int nt = 0; nt < 8; nt++)
#pragma unroll
            for (int q = 0; q < 4; q++) o[mt][nt][q] = 0.0f;

    constexpr int NIT = T_SEQ / 64;   // 32
    for (int kt64 = 0; kt64 < NIT; kt64++) {
        if (kt64 + 1 < NIT) { CP_WAIT1(); } else { CP_WAIT0(); }
        __syncthreads();            // kv(kt64) visible CTA-wide; prior tile's reads done
        if (kt64 + 2 < NIT) issue_kv(kt64 + 2, (kt64 + 2) % 3);
        const uint32_t kvb = sb + 32768 + (kt64 % 3) * ATTN_KV_BUF;

        // ---- S2 = (Q*8*log2e) K^T, 3-term ----
        float s[2][8][4];
#pragma unroll
        for (int mt = 0; mt < 2; mt++)
#pragma unroll
            for (int nt = 0; nt < 8; nt++)
#pragma unroll
                for (int q = 0; q < 4; q++) s[mt][nt][q] = 0.0f;

#pragma unroll
        for (int kt = 0; kt < 4; kt++) {
            uint32_t qa[2][4], qb[2][4];
#pragma unroll
            for (int mt = 0; mt < 2; mt++) {
                const uint32_t soQ = swz(wrow + mt * 16 + laA, kt * 32 + lbA);
                ldsm4(qa[mt], sb + QHo + soQ);
                ldsm4(qb[mt], sb + QLo + soQ);
            }
#pragma unroll
            for (int ntp = 0; ntp < 4; ntp++) {
                const uint32_t soK = swz(ntp * 16 + laB, kt * 32 + lbB);
                uint32_t kH[4], kL[4];
                ldsm4(kH, kvb + KHo + soK);
                ldsm4(kL, kvb + KLo + soK);
                mma_f16(s[0][2 * ntp],     qa[0], kH[0], kH[1]);
                mma_f16(s[1][2 * ntp],     qa[1], kH[0], kH[1]);
                mma_f16(s[0][2 * ntp + 1], qa[0], kH[2], kH[3]);
                mma_f16(s[1][2 * ntp + 1], qa[1], kH[2], kH[3]);
                mma_f16(s[0][2 * ntp],     qa[0], kL[0], kL[1]);
                mma_f16(s[1][2 * ntp],     qa[1], kL[0], kL[1]);
                mma_f16(s[0][2 * ntp + 1], qa[0], kL[2], kL[3]);
                mma_f16(s[1][2 * ntp + 1], qa[1], kL[2], kL[3]);
                mma_f16(s[0][2 * ntp],     qb[0], kH[0], kH[1]);
                mma_f16(s[1][2 * ntp],     qb[1], kH[0], kH[1]);
                mma_f16(s[0][2 * ntp + 1], qb[0], kH[2], kH[3]);
                mma_f16(s[1][2 * ntp + 1], qb[1], kH[2], kH[3]);
            }
        }

        // ---- online softmax (base-2; registers; quad shfl reduce) ----
        float alpha[2][2];
#pragma unroll
        for (int mt = 0; mt < 2; mt++) {
            float mx0 = -1e30f, mx1 = -1e30f;
#pragma unroll
            for (int nt = 0; nt < 8; nt++) {
                mx0 = fmaxf(mx0, fmaxf(s[mt][nt][0], s[mt][nt][1]));
                mx1 = fmaxf(mx1, fmaxf(s[mt][nt][2], s[mt][nt][3]));
            }
            mx0 = fmaxf(mx0, __shfl_xor_sync(0xffffffffu, mx0, 1));
            mx0 = fmaxf(mx0, __shfl_xor_sync(0xffffffffu, mx0, 2));
            mx1 = fmaxf(mx1, __shfl_xor_sync(0xffffffffu, mx1, 1));
            mx1 = fmaxf(mx1, __shfl_xor_sync(0xffffffffu, mx1, 2));

            const float mn0 = fmaxf(mS[mt][0], mx0);
            const float mn1 = fmaxf(mS[mt][1], mx1);
            alpha[mt][0] = ex2f(mS[mt][0] - mn0);
            alpha[mt][1] = ex2f(mS[mt][1] - mn1);
            mS[mt][0] = mn0; mS[mt][1] = mn1;

            float rs0 = 0.0f, rs1 = 0.0f;
#pragma unroll
            for (int nt = 0; nt < 8; nt++) {
                float p0 = ex2f(s[mt][nt][0] - mn0);
                float p1 = ex2f(s[mt][nt][1] - mn0);
                float p2 = ex2f(s[mt][nt][2] - mn1);
                float p3 = ex2f(s[mt][nt][3] - mn1);
                s[mt][nt][0] = p0; s[mt][nt][1] = p1; s[mt][nt][2] = p2; s[mt][nt][3] = p3;
                rs0 += p0 + p1;
                rs1 += p2 + p3;
            }
            rs0 += __shfl_xor_sync(0xffffffffu, rs0, 1);
            rs0 += __shfl_xor_sync(0xffffffffu, rs0, 2);
            rs1 += __shfl_xor_sync(0xffffffffu, rs1, 1);
            rs1 += __shfl_xor_sync(0xffffffffu, rs1, 2);
            lS[mt][0] = lS[mt][0] * alpha[mt][0] + rs0;
            lS[mt][1] = lS[mt][1] * alpha[mt][1] + rs1;

#pragma unroll
            for (int nt = 0; nt < 8; nt++) {
                o[mt][nt][0] *= alpha[mt][0]; o[mt][nt][1] *= alpha[mt][0];
                o[mt][nt][2] *= alpha[mt][1]; o[mt][nt][3] *= alpha[mt][1];
            }
        }

        // ---- O += P V : single-term (P hi only) ----
#pragma unroll
        for (int kt = 0; kt < 4; kt++) {
            uint32_t ph[2][4];
#pragma unroll
            for (int mt = 0; mt < 2; mt++) {
                ph[mt][0] = packh2(s[mt][2 * kt][0],     s[mt][2 * kt][1]);
                ph[mt][1] = packh2(s[mt][2 * kt][2],     s[mt][2 * kt][3]);
                ph[mt][2] = packh2(s[mt][2 * kt + 1][0], s[mt][2 * kt + 1][1]);
                ph[mt][3] = packh2(s[mt][2 * kt + 1][2], s[mt][2 * kt + 1][3]);
            }
#pragma unroll
            for (int ntp = 0; ntp < 4; ntp++) {
                const uint32_t soV = swz(ntp * 16 + laB, kt * 32 + lbB);
                uint32_t vv[4];
                ldsm4(vv, kvb + VHo + soV);
                mma_f16(o[0][2 * ntp],     ph[0], vv[0], vv[1]);
                mma_f16(o[1][2 * ntp],     ph[1], vv[0], vv[1]);
                mma_f16(o[0][2 * ntp + 1], ph[0], vv[2], vv[3]);
                mma_f16(o[1][2 * ntp + 1], ph[1], vv[2], vv[3]);
            }
        }
    }

    // Writeback -> g_oh only
    const int b = bh / NH;
    const int h = bh - b * NH;
#pragma unroll
    for (int mt = 0; mt < 2; mt++) {
        const float li0 = 1.0f / lS[mt][0];
        const float li1 = 1.0f / lS[mt][1];
        const int t_r = t0 + wrow + mt * 16 + r;
#pragma unroll
        for (int nt = 0; nt < 8; nt++) {
            const int col = h * DH + nt * 8 + 2 * (lane & 3);
            uint32_t h0 = packh2(o[mt][nt][0] * li0, o[mt][nt][1] * li0);
            uint32_t h1 = packh2(o[mt][nt][2] * li1, o[mt][nt][3] * li1);
            size_t p0 = ((size_t)b * T_SEQ + t_r) * DMODEL + col;
            size_t p1 = ((size_t)b * T_SEQ + t_r + 8) * DMODEL + col;
            *reinterpret_cast<uint32_t*>(g_oh + p0) = h0;
            *reinterpret_cast<uint32_t*>(g_oh + p1) = h1;
        }
    }
}

// ---------------------------------------------------------------------------
extern "C" void kernel_launch(void* const* d_in, const int* in_sizes, int n_in,
                              void* d_out, int out_size) {
    const float* x     = (const float*)d_in[0];   // [4, 2048, 768]
    const float* w_qkv = (const float*)d_in[1];   // [2304, 768]
    const float* w_out = (const float*)d_in[2];   // [768, 768]
    float* out = (float*)d_out;                   // [4, 2048, 768]

    constexpr int SMEM_QK  = 2 * (2 * 128 * 128 + 2 * 64 * 128);   // 98304
    constexpr int SMEM_1T  = 2 * (128 * 128 + 64 * 128);           // 49152

    cudaFuncSetAttribute((const void*)gemm_mma<0>,
                         cudaFuncAttributeMaxDynamicSharedMemorySize, SMEM_QK);
    cudaFuncSetAttribute((const void*)gemm_mma<2>,
                         cudaFuncAttributeMaxDynamicSharedMemorySize, SMEM_1T);
    cudaFuncSetAttribute((const void*)gemm_mma<1>,
                         cudaFuncAttributeMaxDynamicSharedMemorySize, SMEM_1T);
    cudaFuncSetAttribute((const void*)attn_mma,
                         cudaFuncAttributeMaxDynamicSharedMemorySize, ATTN_SMEM_BYTES);

    split_all<<<2048, 256>>>(x, w_qkv, w_out);
    gemm_mma<0><<<dim3(64, 24), 128, SMEM_QK>>>(nullptr);   // Q,K (3-term)
    gemm_mma<2><<<dim3(64, 12), 128, SMEM_1T>>>(nullptr);   // V (1-term)
    attn_mma<<<dim3(16, 48), 128, ATTN_SMEM_BYTES>>>();
    gemm_mma<1><<<dim3(64, 12), 128, SMEM_1T>>>(out);       // out proj (1-term)
}

// round 17
// speedup vs baseline: 1.0290x; 1.0290x over previous
#include <cuda_runtime.h>
#include <cuda_fp16.h>
#include <cstdint>

#define T_SEQ  2048
#define NB     4
#define NH     12
#define DH     64
#define DMODEL 768
#define BHN    (NB * NH)   // 48

// 8 * log2(e): softmax computed in base-2 domain
#define QSCALE 11.5415603f

// ---------------------------------------------------------------------------
// Device-global scratch. fp16 hi/lo splits (lo only where needed).
// ---------------------------------------------------------------------------
__device__ uint16_t g_xh[(size_t)NB * T_SEQ * DMODEL];
__device__ uint16_t g_xl[(size_t)NB * T_SEQ * DMODEL];
__device__ uint16_t g_wqh[(size_t)3 * DMODEL * DMODEL];
__device__ uint16_t g_wql[(size_t)3 * DMODEL * DMODEL];
__device__ uint16_t g_woh[(size_t)DMODEL * DMODEL];

__device__ uint16_t g_qh[(size_t)BHN * T_SEQ * DH];   // Q pre-scaled by 8*log2(e)
__device__ uint16_t g_ql[(size_t)BHN * T_SEQ * DH];
__device__ uint16_t g_kh[(size_t)BHN * T_SEQ * DH];
__device__ uint16_t g_kl[(size_t)BHN * T_SEQ * DH];
__device__ uint16_t g_vth[(size_t)BHN * DH * T_SEQ];  // V^T: [bh][dh][t] (hi only)

__device__ uint16_t g_oh[(size_t)NB * T_SEQ * DMODEL]; // attention out (hi only)

// ---------------------------------------------------------------------------
// Helpers
// ---------------------------------------------------------------------------
__device__ __forceinline__ uint32_t smem_u32(const void* p) {
    uint32_t a;
    asm("{ .reg .u64 t; cvta.to.shared.u64 t, %1; cvt.u32.u64 %0, t; }"
        : "=r"(a) : "l"(p));
    return a;
}

__device__ __forceinline__ float ex2f(float x) {
    float y;
    asm("ex2.approx.f32 %0, %1;" : "=f"(y) : "f"(x));
    return y;
}

__device__ __forceinline__ uint32_t packh2(float x0, float x1) {
    __half2 hh = __floats2half2_rn(x0, x1);
    return *reinterpret_cast<uint32_t*>(&hh);
}

__device__ __forceinline__ void split2(float x0, float x1, uint32_t& h, uint32_t& l) {
    __half2 hh = __floats2half2_rn(x0, x1);
    __half2 ll = __floats2half2_rn(x0 - __low2float(hh), x1 - __high2float(hh));
    h = *reinterpret_cast<uint32_t*>(&hh);
    l = *reinterpret_cast<uint32_t*>(&ll);
}

// m16n8k16 fp16 mma, fp32 accum (non-volatile: schedulable).
__device__ __forceinline__ void mma_f16(float* d, const uint32_t* a, uint32_t b0, uint32_t b1) {
    asm("mma.sync.aligned.m16n8k16.row.col.f32.f16.f16.f32 "
        "{%0,%1,%2,%3}, {%4,%5,%6,%7}, {%8,%9}, {%0,%1,%2,%3};"
        : "+f"(d[0]), "+f"(d[1]), "+f"(d[2]), "+f"(d[3])
        : "r"(a[0]), "r"(a[1]), "r"(a[2]), "r"(a[3]), "r"(b0), "r"(b1));
}

// ldmatrix x4 (volatile: preserves ordering vs smem writes/barriers)
__device__ __forceinline__ void ldsm4(uint32_t* r, uint32_t addr) {
    asm volatile("ldmatrix.sync.aligned.m8n8.x4.shared.b16 {%0,%1,%2,%3}, [%4];"
                 : "=r"(r[0]), "=r"(r[1]), "=r"(r[2]), "=r"(r[3]) : "r"(addr));
}

// Swizzled smem byte offset within a tile of 128B rows
__device__ __forceinline__ uint32_t swz(int row, int byteoff) {
    return (uint32_t)(row * 128 + (byteoff ^ ((row & 7) << 4)));
}

#define CP_ASYNC16(dst_u32, src_ptr) \
    asm volatile("cp.async.cg.shared.global [%0], [%1], 16;" \
                 :: "r"(dst_u32), "l"(src_ptr) : "memory")
#define CP_COMMIT() asm volatile("cp.async.commit_group;" ::: "memory")
#define CP_WAIT1()  asm volatile("cp.async.wait_group 1;" ::: "memory")
#define CP_WAIT0()  asm volatile("cp.async.wait_group 0;" ::: "memory")

// ---------------------------------------------------------------------------
// Split fp32 -> fp16 (hi, lo); w_out keeps hi only.
// ---------------------------------------------------------------------------
__global__ void split_all(const float* __restrict__ x, const float* __restrict__ wq,
                          const float* __restrict__ wo) {
    const int N1 = (NB * T_SEQ * DMODEL) / 4;
    const int N2 = (3 * DMODEL * DMODEL) / 4;
    const int N3 = (DMODEL * DMODEL) / 4;
    const int tot = N1 + N2 + N3;
    for (int i = blockIdx.x * blockDim.x + threadIdx.x; i < tot; i += gridDim.x * blockDim.x) {
        const float4* src;
        uint16_t *dh, *dl;
        int j;
        if (i < N1)           { src = (const float4*)x;  j = i;           dh = g_xh;  dl = g_xl; }
        else if (i < N1 + N2) { src = (const float4*)wq; j = i - N1;      dh = g_wqh; dl = g_wql; }
        else                  { src = (const float4*)wo; j = i - N1 - N2; dh = g_woh; dl = nullptr; }
        float4 v = src[j];
        uint32_t h0, l0, h1, l1;
        split2(v.x, v.y, h0, l0);
        split2(v.z, v.w, h1, l1);
        *reinterpret_cast<uint2*>(dh + 4 * (size_t)j) = uint2{h0, h1};
        if (dl) *reinterpret_cast<uint2*>(dl + 4 * (size_t)j) = uint2{l0, l1};
    }
}

// ---------------------------------------------------------------------------
// mma.sync split-fp16 GEMM, cp.async double-buffered, ldmatrix fragments,
// register-level software pipelining; single barrier per K-chunk.
// CTA 128x64, 128 thr, warps 2m x 2n, warp tile 64x32.
// MODE 0: Q,K columns of QKV (grid.y = 24). 3-term.  Stage 48KB x2.
// MODE 2: V columns of QKV (grid.y = 12). 1-term.    Stage 24KB x2. 4 CTAs/SM.
// MODE 1: output projection (grid.y = 12). 1-term.   Stage 24KB x2. 4 CTAs/SM.
// ---------------------------------------------------------------------------
template <int MODE, int MINB>
__global__ void __launch_bounds__(128, MINB) gemm_mma(float* __restrict__ C) {
    extern __shared__ char smem[];
    const uint32_t sb = smem_u32(smem);
    constexpr int CTAM = 128, CTAN = 64, NTHR = 128;
    constexpr int MT = 4;
    constexpr bool T3 = (MODE == 0);
    constexpr int NB_A = T3 ? 2 : 1;
    constexpr int NB_B = T3 ? 2 : 1;
    constexpr int AREG = NB_A * CTAM * 128;
    constexpr int AHo = 0, ALo = CTAM * 128;
    constexpr int BHo = AREG, BLo = AREG + CTAN * 128;
    constexpr int STAGE = AREG + NB_B * CTAN * 128;

    const int tid = threadIdx.x;
    const int lane = tid & 31;
    const int wid = tid >> 5;
    const int m0 = blockIdx.x * CTAM;
    const int by = blockIdx.y;
    const int koff = (MODE == 2) ? (24 + by) : by;   // QKV column group
    const int wm = (wid >> 1) * 64;
    const int wn = (wid & 1) * 32;

    const int laA = lane & 15;
    const int lbA = (lane >> 4) * 16;
    const int laB = (lane >> 4) * 8 + (lane & 7);
    const int lbB = ((lane >> 3) & 1) * 16;

    const uint16_t* Ah = (MODE == 1) ? g_oh : g_xh;
    const uint16_t* Al = g_xl;
    const uint16_t* Bh = (MODE == 1) ? g_woh : g_wqh;
    const uint16_t* Bl = g_wql;

    auto issue_stage = [&](int c, int buf) {
        const int k0 = c * 64;
        const uint32_t base = sb + buf * STAGE;
#pragma unroll
        for (int it = 0; it < CTAM * 8 / NTHR; it++) {
            const int idx = it * NTHR + tid;
            const int row = idx >> 3;
            const int ch = idx & 7;
            const uint32_t so = swz(row, ch * 16);
            CP_ASYNC16(base + AHo + so, Ah + (size_t)(m0 + row) * DMODEL + k0 + ch * 8);
            if (T3)
                CP_ASYNC16(base + ALo + so, Al + (size_t)(m0 + row) * DMODEL + k0 + ch * 8);
        }
#pragma unroll
        for (int it = 0; it < CTAN * 8 / NTHR; it++) {
            const int idx = it * NTHR + tid;
            const int row = idx >> 3;
            const int ch = idx & 7;
            const uint32_t so = swz(row, ch * 16);
            const int grow = (MODE == 1) ? (by * CTAN + row) : (row * 36 + koff);
            CP_ASYNC16(base + BHo + so, Bh + (size_t)grow * DMODEL + k0 + ch * 8);
            if (T3)
                CP_ASYNC16(base + BLo + so, Bl + (size_t)grow * DMODEL + k0 + ch * 8);
        }
        CP_COMMIT();
    };

    float acc[MT][4][4];
#pragma unroll
    for (int mt = 0; mt < MT; mt++)
#pragma unroll
        for (int nt = 0; nt < 4; nt++)
#pragma unroll
            for (int q = 0; q < 4; q++) acc[mt][nt][q] = 0.0f;

    issue_stage(0, 0);

    for (int c = 0; c < 12; c++) {
        CP_WAIT0();                 // only stage c outstanding at this point
        __syncthreads();            // CTA-wide visibility + buffer reuse safety
        if (c + 1 < 12) issue_stage(c + 1, (c + 1) & 1);
        const uint32_t bpu = sb + (c & 1) * STAGE;

        uint32_t aH[2][MT][4], aL[2][MT][4], bH[2][2][4], bL[2][2][4];
        auto ldkt = [&](int kt, int p) {
#pragma unroll
            for (int mt = 0; mt < MT; mt++) {
                const uint32_t soA = swz(wm + mt * 16 + laA, kt * 32 + lbA);
                ldsm4(aH[p][mt], bpu + AHo + soA);
                if (T3) ldsm4(aL[p][mt], bpu + ALo + soA);
            }
#pragma unroll
            for (int ntp = 0; ntp < 2; ntp++) {
                const uint32_t soB = swz(wn + ntp * 16 + laB, kt * 32 + lbB);
                ldsm4(bH[p][ntp], bpu + BHo + soB);
                if (T3) ldsm4(bL[p][ntp], bpu + BLo + soB);
            }
        };
        ldkt(0, 0);

#pragma unroll
        for (int kt = 0; kt < 4; kt++) {
            const int p = kt & 1;
            if (kt < 3) ldkt(kt + 1, p ^ 1);
#pragma unroll
            for (int ntp = 0; ntp < 2; ntp++) {
#pragma unroll
                for (int mt = 0; mt < MT; mt++) {
                    mma_f16(acc[mt][2 * ntp],     aH[p][mt], bH[p][ntp][0], bH[p][ntp][1]);
                    mma_f16(acc[mt][2 * ntp + 1], aH[p][mt], bH[p][ntp][2], bH[p][ntp][3]);
                }
                if (T3) {
#pragma unroll
                    for (int mt = 0; mt < MT; mt++) {
                        mma_f16(acc[mt][2 * ntp],     aH[p][mt], bL[p][ntp][0], bL[p][ntp][1]);
                        mma_f16(acc[mt][2 * ntp + 1], aH[p][mt], bL[p][ntp][2], bL[p][ntp][3]);
                    }
#pragma unroll
                    for (int mt = 0; mt < MT; mt++) {
                        mma_f16(acc[mt][2 * ntp],     aL[p][mt], bH[p][ntp][0], bH[p][ntp][1]);
                        mma_f16(acc[mt][2 * ntp + 1], aL[p][mt], bH[p][ntp][2], bH[p][ntp][3]);
                    }
                }
            }
        }
    }

    // Epilogue
    const int r = lane >> 2;
#pragma unroll
    for (int mt = 0; mt < MT; mt++) {
        const int mrow = m0 + wm + mt * 16 + r;
#pragma unroll
        for (int nt = 0; nt < 4; nt++) {
            const int nl = wn + nt * 8 + 2 * (lane & 3);
            float d0 = acc[mt][nt][0], d1 = acc[mt][nt][1];
            float d2 = acc[mt][nt][2], d3 = acc[mt][nt][3];
            if (MODE != 1) {
                const int dh = nl;
                const int k3 = koff / 12;
                const int h = koff - 12 * k3;
                const int b = mrow >> 11;
                const int t = mrow & 2047;
                const int bhI = b * NH + h;
                if (k3 == 0) { d0 *= QSCALE; d1 *= QSCALE; d2 *= QSCALE; d3 *= QSCALE; }
                if (MODE == 2) {
                    uint32_t h0 = packh2(d0, d1), h1 = packh2(d2, d3);
                    size_t q0 = ((size_t)bhI * DH + dh) * T_SEQ + t;
                    size_t q1 = ((size_t)bhI * DH + dh + 1) * T_SEQ + t;
                    g_vth[q0] = (uint16_t)h0;      g_vth[q1] = (uint16_t)(h0 >> 16);
                    g_vth[q0 + 8] = (uint16_t)h1;  g_vth[q1 + 8] = (uint16_t)(h1 >> 16);
                } else {
                    uint32_t h0, l0, h1, l1;
                    split2(d0, d1, h0, l0);
                    split2(d2, d3, h1, l1);
                    uint16_t* dsth = (k3 == 0) ? g_qh : g_kh;
                    uint16_t* dstl = (k3 == 0) ? g_ql : g_kl;
                    size_t p0 = ((size_t)bhI * T_SEQ + t) * DH + dh;
                    size_t p1 = ((size_t)bhI * T_SEQ + t + 8) * DH + dh;
                    *reinterpret_cast<uint32_t*>(dsth + p0) = h0;
                    *reinterpret_cast<uint32_t*>(dstl + p0) = l0;
                    *reinterpret_cast<uint32_t*>(dsth + p1) = h1;
                    *reinterpret_cast<uint32_t*>(dstl + p1) = l1;
                }
            } else {
                float2 p0{d0, d1}, p1{d2, d3};
                *reinterpret_cast<float2*>(C + (size_t)mrow * DMODEL + by * CTAN + nl) = p0;
                *reinterpret_cast<float2*>(C + (size_t)(mrow + 8) * DMODEL + by * CTAN + nl) = p1;
            }
        }
    }
}

// ---------------------------------------------------------------------------
// Flash attention (round-15 base) + within-kt register double-buffering of
// K and V fragments (prefetch ntp+1 over the current MMA bundle).
// 128 threads (4 warps), warp tile 32 q-rows x 64 keys.
// QK^T 3-term, PV single-term. Base-2 softmax. 3-stage cp.async KV ring.
// ---------------------------------------------------------------------------
#define ATTN_KV_BUF   24576
#define ATTN_SMEM_BYTES (32768 + 3 * ATTN_KV_BUF)   // Q(32K) + 3 KV stages

__global__ void __launch_bounds__(128) attn_mma() {
    extern __shared__ char smem[];
    const uint32_t sb = smem_u32(smem);
    const int QHo = 0, QLo = 16384;
    const int KHo = 0, KLo = 8192, VHo = 16384;     // within KV stage

    const int tid = threadIdx.x;
    const int lane = tid & 31;
    const int wid = tid >> 5;
    const int r = lane >> 2;
    const int bh = blockIdx.y;
    const int t0 = blockIdx.x * 128;
    const int wrow = wid * 32;

    const int laA = lane & 15;
    const int lbA = (lane >> 4) * 16;
    const int laB = (lane >> 4) * 8 + (lane & 7);
    const int lbB = ((lane >> 3) & 1) * 16;

    const uint16_t* kh = g_kh + (size_t)bh * T_SEQ * DH;
    const uint16_t* kl = g_kl + (size_t)bh * T_SEQ * DH;
    const uint16_t* vh = g_vth + (size_t)bh * DH * T_SEQ;

    auto issue_kv = [&](int kt, int buf) {
        const uint32_t base = sb + 32768 + buf * ATTN_KV_BUF;
#pragma unroll
        for (int it = 0; it < 4; it++) {
            const int idx = it * 128 + tid;
            const int row = idx >> 3;
            const int ch = idx & 7;
            const uint32_t so = swz(row, ch * 16);
            CP_ASYNC16(base + KHo + so, kh + (size_t)(kt * 64 + row) * DH + ch * 8);
            CP_ASYNC16(base + KLo + so, kl + (size_t)(kt * 64 + row) * DH + ch * 8);
            CP_ASYNC16(base + VHo + so, vh + (size_t)row * T_SEQ + kt * 64 + ch * 8);
        }
        CP_COMMIT();
    };

    issue_kv(0, 0);
    issue_kv(1, 1);

    const uint16_t* qhp = g_qh + ((size_t)bh * T_SEQ + t0) * DH;
    const uint16_t* qlp = g_ql + ((size_t)bh * T_SEQ + t0) * DH;
#pragma unroll
    for (int it = 0; it < 8; it++) {
        const int idx = it * 128 + tid;
        const int row = idx >> 3;
        const int ch = idx & 7;
        const uint32_t so = swz(row, ch * 16);
        *reinterpret_cast<uint4*>(smem + QHo + so) =
            *(reinterpret_cast<const uint4*>(qhp + (size_t)row * DH) + ch);
        *reinterpret_cast<uint4*>(smem + QLo + so) =
            *(reinterpret_cast<const uint4*>(qlp + (size_t)row * DH) + ch);
    }

    float mS[2][2], lS[2][2];
#pragma unroll
    for (int mt = 0; mt < 2; mt++) { mS[mt][0] = mS[mt][1] = -1e30f; lS[mt][0] = lS[mt][1] = 0.0f; }

    float o[2][8][4];
#pragma unroll
    for (int mt = 0; mt < 2; mt++)
#pragma unroll
        for (int nt = 0; nt < 8; nt++)
#pragma unroll
            for (int q = 0; q < 4; q++) o[mt][nt][q] = 0.0f;

    constexpr int NIT = T_SEQ / 64;   // 32
    for (int kt64 = 0; kt64 < NIT; kt64++) {
        if (kt64 + 1 < NIT) { CP_WAIT1(); } else { CP_WAIT0(); }
        __syncthreads();            // kv(kt64) visible CTA-wide; prior tile's reads done
        if (kt64 + 2 < NIT) issue_kv(kt64 + 2, (kt64 + 2) % 3);
        const uint32_t kvb = sb + 32768 + (kt64 % 3) * ATTN_KV_BUF;

        // ---- S2 = (Q*8*log2e) K^T, 3-term; K frags double-buffered in regs ----
        float s[2][8][4];
#pragma unroll
        for (int mt = 0; mt < 2; mt++)
#pragma unroll
            for (int nt = 0; nt < 8; nt++)
#pragma unroll
                for (int q = 0; q < 4; q++) s[mt][nt][q] = 0.0f;

#pragma unroll
        for (int kt = 0; kt < 4; kt++) {
            uint32_t qa[2][4], qb[2][4];
#pragma unroll
            for (int mt = 0; mt < 2; mt++) {
                const uint32_t soQ = swz(wrow + mt * 16 + laA, kt * 32 + lbA);
                ldsm4(qa[mt], sb + QHo + soQ);
                ldsm4(qb[mt], sb + QLo + soQ);
            }
            uint32_t kH[2][4], kL[2][4];
            {
                const uint32_t soK = swz(laB, kt * 32 + lbB);
                ldsm4(kH[0], kvb + KHo + soK);
                ldsm4(kL[0], kvb + KLo + soK);
            }
#pragma unroll
            for (int ntp = 0; ntp < 4; ntp++) {
                const int p = ntp & 1;
                if (ntp < 3) {
                    const uint32_t soK = swz((ntp + 1) * 16 + laB, kt * 32 + lbB);
                    ldsm4(kH[p ^ 1], kvb + KHo + soK);
                    ldsm4(kL[p ^ 1], kvb + KLo + soK);
                }
                mma_f16(s[0][2 * ntp],     qa[0], kH[p][0], kH[p][1]);
                mma_f16(s[1][2 * ntp],     qa[1], kH[p][0], kH[p][1]);
                mma_f16(s[0][2 * ntp + 1], qa[0], kH[p][2], kH[p][3]);
                mma_f16(s[1][2 * ntp + 1], qa[1], kH[p][2], kH[p][3]);
                mma_f16(s[0][2 * ntp],     qa[0], kL[p][0], kL[p][1]);
                mma_f16(s[1][2 * ntp],     qa[1], kL[p][0], kL[p][1]);
                mma_f16(s[0][2 * ntp + 1], qa[0], kL[p][2], kL[p][3]);
                mma_f16(s[1][2 * ntp + 1], qa[1], kL[p][2], kL[p][3]);
                mma_f16(s[0][2 * ntp],     qb[0], kH[p][0], kH[p][1]);
                mma_f16(s[1][2 * ntp],     qb[1], kH[p][0], kH[p][1]);
                mma_f16(s[0][2 * ntp + 1], qb[0], kH[p][2], kH[p][3]);
                mma_f16(s[1][2 * ntp + 1], qb[1], kH[p][2], kH[p][3]);
            }
        }

        // ---- online softmax (base-2; registers; quad shfl reduce) ----
        float alpha[2][2];
#pragma unroll
        for (int mt = 0; mt < 2; mt++) {
            float mx0 = -1e30f, mx1 = -1e30f;
#pragma unroll
            for (int nt = 0; nt < 8; nt++) {
                mx0 = fmaxf(mx0, fmaxf(s[mt][nt][0], s[mt][nt][1]));
                mx1 = fmaxf(mx1, fmaxf(s[mt][nt][2], s[mt][nt][3]));
            }
            mx0 = fmaxf(mx0, __shfl_xor_sync(0xffffffffu, mx0, 1));
            mx0 = fmaxf(mx0, __shfl_xor_sync(0xffffffffu, mx0, 2));
            mx1 = fmaxf(mx1, __shfl_xor_sync(0xffffffffu, mx1, 1));
            mx1 = fmaxf(mx1, __shfl_xor_sync(0xffffffffu, mx1, 2));

            const float mn0 = fmaxf(mS[mt][0], mx0);
            const float mn1 = fmaxf(mS[mt][1], mx1);
            alpha[mt][0] = ex2f(mS[mt][0] - mn0);
            alpha[mt][1] = ex2f(mS[mt][1] - mn1);
            mS[mt][0] = mn0; mS[mt][1] = mn1;

            float rs0 = 0.0f, rs1 = 0.0f;
#pragma unroll
            for (int nt = 0; nt < 8; nt++) {
                float p0 = ex2f(s[mt][nt][0] - mn0);
                float p1 = ex2f(s[mt][nt][1] - mn0);
                float p2 = ex2f(s[mt][nt][2] - mn1);
                float p3 = ex2f(s[mt][nt][3] - mn1);
                s[mt][nt][0] = p0; s[mt][nt][1] = p1; s[mt][nt][2] = p2; s[mt][nt][3] = p3;
                rs0 += p0 + p1;
                rs1 += p2 + p3;
            }
            rs0 += __shfl_xor_sync(0xffffffffu, rs0, 1);
            rs0 += __shfl_xor_sync(0xffffffffu, rs0, 2);
            rs1 += __shfl_xor_sync(0xffffffffu, rs1, 1);
            rs1 += __shfl_xor_sync(0xffffffffu, rs1, 2);
            lS[mt][0] = lS[mt][0] * alpha[mt][0] + rs0;
            lS[mt][1] = lS[mt][1] * alpha[mt][1] + rs1;

#pragma unroll
            for (int nt = 0; nt < 8; nt++) {
                o[mt][nt][0] *= alpha[mt][0]; o[mt][nt][1] *= alpha[mt][0];
                o[mt][nt][2] *= alpha[mt][1]; o[mt][nt][3] *= alpha[mt][1];
            }
        }

        // ---- O += P V : single-term; V frags double-buffered in regs ----
#pragma unroll
        for (int kt = 0; kt < 4; kt++) {
            uint32_t ph[2][4];
#pragma unroll
            for (int mt = 0; mt < 2; mt++) {
                ph[mt][0] = packh2(s[mt][2 * kt][0],     s[mt][2 * kt][1]);
                ph[mt][1] = packh2(s[mt][2 * kt][2],     s[mt][2 * kt][3]);
                ph[mt][2] = packh2(s[mt][2 * kt + 1][0], s[mt][2 * kt + 1][1]);
                ph[mt][3] = packh2(s[mt][2 * kt + 1][2], s[mt][2 * kt + 1][3]);
            }
            uint32_t vv[2][4];
            ldsm4(vv[0], kvb + VHo + swz(laB, kt * 32 + lbB));
#pragma unroll
            for (int ntp = 0; ntp < 4; ntp++) {
                const int p = ntp & 1;
                if (ntp < 3)
                    ldsm4(vv[p ^ 1], kvb + VHo + swz((ntp + 1) * 16 + laB, kt * 32 + lbB));
                mma_f16(o[0][2 * ntp],     ph[0], vv[p][0], vv[p][1]);
                mma_f16(o[1][2 * ntp],     ph[1], vv[p][0], vv[p][1]);
                mma_f16(o[0][2 * ntp + 1], ph[0], vv[p][2], vv[p][3]);
                mma_f16(o[1][2 * ntp + 1], ph[1], vv[p][2], vv[p][3]);
            }
        }
    }

    // Writeback -> g_oh only
    const int b = bh / NH;
    const int h = bh - b * NH;
#pragma unroll
    for (int mt = 0; mt < 2; mt++) {
        const float li0 = 1.0f / lS[mt][0];
        const float li1 = 1.0f / lS[mt][1];
        const int t_r = t0 + wrow + mt * 16 + r;
#pragma unroll
        for (int nt = 0; nt < 8; nt++) {
            const int col = h * DH + nt * 8 + 2 * (lane & 3);
            uint32_t h0 = packh2(o[mt][nt][0] * li0, o[mt][nt][1] * li0);
            uint32_t h1 = packh2(o[mt][nt][2] * li1, o[mt][nt][3] * li1);
            size_t p0 = ((size_t)b * T_SEQ + t_r) * DMODEL + col;
            size_t p1 = ((size_t)b * T_SEQ + t_r + 8) * DMODEL + col;
            *reinterpret_cast<uint32_t*>(g_oh + p0) = h0;
            *reinterpret_cast<uint32_t*>(g_oh + p1) = h1;
        }
    }
}

// ---------------------------------------------------------------------------
extern "C" void kernel_launch(void* const* d_in, const int* in_sizes, int n_in,
                              void* d_out, int out_size) {
    const float* x     = (const float*)d_in[0];   // [4, 2048, 768]
    const float* w_qkv = (const float*)d_in[1];   // [2304, 768]
    const float* w_out = (const float*)d_in[2];   // [768, 768]
    float* out = (float*)d_out;                   // [4, 2048, 768]

    constexpr int SMEM_QK  = 2 * (2 * 128 * 128 + 2 * 64 * 128);   // 98304
    constexpr int SMEM_1T  = 2 * (128 * 128 + 64 * 128);           // 49152

    cudaFuncSetAttribute((const void*)gemm_mma<0, 1>,
                         cudaFuncAttributeMaxDynamicSharedMemorySize, SMEM_QK);
    cudaFuncSetAttribute((const void*)gemm_mma<2, 4>,
                         cudaFuncAttributeMaxDynamicSharedMemorySize, SMEM_1T);
    cudaFuncSetAttribute((const void*)gemm_mma<1, 4>,
                         cudaFuncAttributeMaxDynamicSharedMemorySize, SMEM_1T);
    cudaFuncSetAttribute((const void*)attn_mma,
                         cudaFuncAttributeMaxDynamicSharedMemorySize, ATTN_SMEM_BYTES);

    split_all<<<2048, 256>>>(x, w_qkv, w_out);
    gemm_mma<0, 1><<<dim3(64, 24), 128, SMEM_QK>>>(nullptr);   // Q,K (3-term)
    gemm_mma<2, 4><<<dim3(64, 12), 128, SMEM_1T>>>(nullptr);   // V (1-term)
    attn_mma<<<dim3(16, 48), 128, ATTN_SMEM_BYTES>>>();
    gemm_mma<1, 4><<<dim3(64, 12), 128, SMEM_1T>>>(out);       // out proj (1-term)
}